// round 1
// baseline (speedup 1.0000x reference)
#include <cuda_runtime.h>
#include <cstdint>
#include <math.h>

// Problem constants
// B=2, S=2048, D=2048, H=16, HD=128, LY=512, DY=2048, H*HD=2048
#define NROWS_X 4096   // B*S
#define NROWS_Y 1024   // B*LY
#define NH      2048   // H*HD

// ---------------- scratch (device globals; no allocation allowed) ----------------
__device__ float g_xq[(size_t)NROWS_X * NH];
__device__ float g_xk[(size_t)NROWS_X * NH];
__device__ float g_xv[(size_t)NROWS_X * NH];
__device__ float g_yk[(size_t)NROWS_Y * NH];
__device__ float g_yv[(size_t)NROWS_Y * NH];
__device__ float g_at[(size_t)NROWS_X * NH];

// ---------------- SGEMM: C[M,N] = A[M,K] @ B[K,N], all row-major -----------------
// 128x128 block tile, BK=8, 256 threads, 8x8 micro-tile. M%128==0, N%128==0, K%8==0.
__global__ __launch_bounds__(256) void sgemm_kernel(
    const float* __restrict__ A, const float* __restrict__ Bm, float* __restrict__ C,
    int M, int N, int K)
{
    __shared__ float As[8][128];   // transposed: As[k][m]
    __shared__ float Bs[8][128];   // Bs[k][n]
    const int t  = threadIdx.x;
    const int tx = t & 15, ty = t >> 4;
    const int m0 = blockIdx.y * 128, n0 = blockIdx.x * 128;
    const int ar = t >> 1,  ac = (t & 1) * 4;   // A tile: 128 rows x 8 cols
    const int br = t >> 5,  bc = (t & 31) * 4;  // B tile: 8 rows x 128 cols

    const float* Ap = A + (size_t)(m0 + ar) * K + ac;
    const float* Bp = Bm + (size_t)br * N + n0 + bc;

    float acc[8][8];
#pragma unroll
    for (int i = 0; i < 8; ++i)
#pragma unroll
        for (int j = 0; j < 8; ++j) acc[i][j] = 0.f;

    for (int k0 = 0; k0 < K; k0 += 8) {
        float4 a4 = *(const float4*)Ap;
        float4 b4 = *(const float4*)Bp;
        Ap += 8;
        Bp += (size_t)8 * N;
        __syncthreads();
        As[ac + 0][ar] = a4.x; As[ac + 1][ar] = a4.y;
        As[ac + 2][ar] = a4.z; As[ac + 3][ar] = a4.w;
        *(float4*)(&Bs[br][bc]) = b4;
        __syncthreads();
#pragma unroll
        for (int kk = 0; kk < 8; ++kk) {
            float a[8], b[8];
            *(float4*)(a)     = *(const float4*)(&As[kk][4 * ty]);
            *(float4*)(a + 4) = *(const float4*)(&As[kk][4 * ty + 64]);
            *(float4*)(b)     = *(const float4*)(&Bs[kk][4 * tx]);
            *(float4*)(b + 4) = *(const float4*)(&Bs[kk][4 * tx + 64]);
#pragma unroll
            for (int i = 0; i < 8; ++i)
#pragma unroll
                for (int j = 0; j < 8; ++j)
                    acc[i][j] = fmaf(a[i], b[j], acc[i][j]);
        }
    }
#pragma unroll
    for (int i = 0; i < 8; ++i) {
        int r = m0 + ((i < 4) ? (4 * ty + i) : (64 + 4 * ty + (i - 4)));
        float* Crow = C + (size_t)r * N + n0;
        *(float4*)(Crow + 4 * tx)      = make_float4(acc[i][0], acc[i][1], acc[i][2], acc[i][3]);
        *(float4*)(Crow + 64 + 4 * tx) = make_float4(acc[i][4], acc[i][5], acc[i][6], acc[i][7]);
    }
}

// --------------- LayerNorm (+ optional RoPE), in place, one block per row --------
__global__ __launch_bounds__(256) void ln_rope_kernel(
    float* __restrict__ X, const float* __restrict__ w, const float* __restrict__ bgain,
    const float* __restrict__ fc, float eps, int do_rope)
{
    const int row = blockIdx.x;
    float* xr = X + (size_t)row * 2048;
    const int t = threadIdx.x;

    float v[8];
    *(float4*)(v)     = *(const float4*)(xr + t * 8);
    *(float4*)(v + 4) = *(const float4*)(xr + t * 8 + 4);

    float s = 0.f, ss = 0.f;
#pragma unroll
    for (int i = 0; i < 8; ++i) { s += v[i]; ss += v[i] * v[i]; }
#pragma unroll
    for (int off = 16; off; off >>= 1) {
        s  += __shfl_xor_sync(0xffffffffu, s, off);
        ss += __shfl_xor_sync(0xffffffffu, ss, off);
    }
    __shared__ float sh[16];
    const int lane = t & 31, wrp = t >> 5;
    if (lane == 0) { sh[wrp] = s; sh[8 + wrp] = ss; }
    __syncthreads();
    s = 0.f; ss = 0.f;
#pragma unroll
    for (int i = 0; i < 8; ++i) { s += sh[i]; ss += sh[8 + i]; }

    const float mean = s * (1.f / 2048.f);
    const float var  = ss * (1.f / 2048.f) - mean * mean;
    const float rs   = rsqrtf(var + eps);

    const int base = t * 8;
    float o[8];
#pragma unroll
    for (int i = 0; i < 8; ++i) {
        int e = base + i;
        o[i] = (v[i] - mean) * rs * w[e] + bgain[e];
    }
    if (do_rope) {
        int sidx = row & 2047;  // row % S
#pragma unroll
        for (int i = 0; i < 8; i += 2) {
            int e = base + i;
            int pidx = (e & 127) >> 1;
            float c  = fc[(sidx * 64 + pidx) * 2 + 0];
            float sn = fc[(sidx * 64 + pidx) * 2 + 1];
            float r0 = o[i] * c - o[i + 1] * sn;
            float r1 = o[i] * sn + o[i + 1] * c;
            o[i] = r0; o[i + 1] = r1;
        }
    }
    *(float4*)(xr + t * 8)     = *(float4*)(o);
    *(float4*)(xr + t * 8 + 4) = *(float4*)(o + 4);
}

// ---------------- fused flash attention (self + gated cross) ---------------------
// Block: (qtile, h, b). 256 threads. TQ=TK=64. Online softmax per query row.
// smem float offsets
#define SM_QS 0          // Qs[64][132]
#define SM_KT 8448       // KsT[128][65]
#define SM_VS 16768      // Vs[64][132]
#define SM_PS 25216      // Ps[64][68]
#define ATTN_SMEM_FLOATS 29568

__device__ __forceinline__ float neginf() { return __int_as_float(0xff800000); }

__device__ __forceinline__ void attn_pass(
    const float* __restrict__ Kp, const float* __restrict__ Vp,
    size_t kvrow0, int ntiles, int hoff,
    float* Qs, float* KsT, float* Vs, float* Ps,
    int tx, int ty, int lane, int wrp,
    float acc[32], float lout[4])
{
    float m[4], l[4];
#pragma unroll
    for (int i = 0; i < 4; ++i) { m[i] = neginf(); l[i] = 0.f; }
#pragma unroll
    for (int i = 0; i < 32; ++i) acc[i] = 0.f;

    const float scale = 0.08838834764831845f;  // 1/sqrt(128)

    for (int kt = 0; kt < ntiles; ++kt) {
        __syncthreads();  // prior-tile reads of KsT/Vs/Ps done (and Qs visible on first iter)
        const float* Kb = Kp + (kvrow0 + (size_t)kt * 64) * 2048 + hoff;
        const float* Vb = Vp + (kvrow0 + (size_t)kt * 64) * 2048 + hoff;
#pragma unroll
        for (int p = 0; p < 8; ++p) {
            int tok = wrp + p * 8;
            float4 k4 = *(const float4*)(Kb + (size_t)tok * 2048 + lane * 4);
            int d0 = lane * 4;
            KsT[(d0 + 0) * 65 + tok] = k4.x;
            KsT[(d0 + 1) * 65 + tok] = k4.y;
            KsT[(d0 + 2) * 65 + tok] = k4.z;
            KsT[(d0 + 3) * 65 + tok] = k4.w;
            float4 v4 = *(const float4*)(Vb + (size_t)tok * 2048 + lane * 4);
            *(float4*)(Vs + tok * 132 + lane * 4) = v4;
        }
        __syncthreads();

        // scores: S[4q][4k] = Q . K^T
        float sc[4][4];
#pragma unroll
        for (int i = 0; i < 4; ++i)
#pragma unroll
            for (int j = 0; j < 4; ++j) sc[i][j] = 0.f;
#pragma unroll 4
        for (int d = 0; d < 128; ++d) {
            float q0 = Qs[(4 * ty + 0) * 132 + d];
            float q1 = Qs[(4 * ty + 1) * 132 + d];
            float q2 = Qs[(4 * ty + 2) * 132 + d];
            float q3 = Qs[(4 * ty + 3) * 132 + d];
            float k0 = KsT[d * 65 + 4 * tx + 0];
            float k1 = KsT[d * 65 + 4 * tx + 1];
            float k2 = KsT[d * 65 + 4 * tx + 2];
            float k3 = KsT[d * 65 + 4 * tx + 3];
            sc[0][0] = fmaf(q0, k0, sc[0][0]); sc[0][1] = fmaf(q0, k1, sc[0][1]);
            sc[0][2] = fmaf(q0, k2, sc[0][2]); sc[0][3] = fmaf(q0, k3, sc[0][3]);
            sc[1][0] = fmaf(q1, k0, sc[1][0]); sc[1][1] = fmaf(q1, k1, sc[1][1]);
            sc[1][2] = fmaf(q1, k2, sc[1][2]); sc[1][3] = fmaf(q1, k3, sc[1][3]);
            sc[2][0] = fmaf(q2, k0, sc[2][0]); sc[2][1] = fmaf(q2, k1, sc[2][1]);
            sc[2][2] = fmaf(q2, k2, sc[2][2]); sc[2][3] = fmaf(q2, k3, sc[2][3]);
            sc[3][0] = fmaf(q3, k0, sc[3][0]); sc[3][1] = fmaf(q3, k1, sc[3][1]);
            sc[3][2] = fmaf(q3, k2, sc[3][2]); sc[3][3] = fmaf(q3, k3, sc[3][3]);
        }

        // online softmax update; row state replicated across the 16 tx lanes
#pragma unroll
        for (int i = 0; i < 4; ++i) {
#pragma unroll
            for (int j = 0; j < 4; ++j) sc[i][j] *= scale;
            float rm = fmaxf(fmaxf(sc[i][0], sc[i][1]), fmaxf(sc[i][2], sc[i][3]));
#pragma unroll
            for (int off = 8; off; off >>= 1)
                rm = fmaxf(rm, __shfl_xor_sync(0xffffffffu, rm, off));
            float mn   = fmaxf(m[i], rm);
            float corr = __expf(m[i] - mn);
            float rsum = 0.f;
#pragma unroll
            for (int j = 0; j < 4; ++j) {
                float p = __expf(sc[i][j] - mn);
                sc[i][j] = p;
                rsum += p;
            }
#pragma unroll
            for (int off = 8; off; off >>= 1)
                rsum += __shfl_xor_sync(0xffffffffu, rsum, off);
            l[i] = l[i] * corr + rsum;
            m[i] = mn;
#pragma unroll
            for (int dd = 0; dd < 8; ++dd) acc[i * 8 + dd] *= corr;
            *(float4*)(Ps + (4 * ty + i) * 68 + 4 * tx) =
                make_float4(sc[i][0], sc[i][1], sc[i][2], sc[i][3]);
        }
        __syncthreads();

        // acc += P @ V : each thread owns 4 queries x 8 dims (dims tx*8..tx*8+7)
#pragma unroll 2
        for (int j = 0; j < 64; ++j) {
            float vv[8];
            *(float4*)(vv)     = *(const float4*)(Vs + j * 132 + tx * 8);
            *(float4*)(vv + 4) = *(const float4*)(Vs + j * 132 + tx * 8 + 4);
#pragma unroll
            for (int i = 0; i < 4; ++i) {
                float p = Ps[(4 * ty + i) * 68 + j];
#pragma unroll
                for (int dd = 0; dd < 8; ++dd)
                    acc[i * 8 + dd] = fmaf(p, vv[dd], acc[i * 8 + dd]);
            }
        }
    }
#pragma unroll
    for (int i = 0; i < 4; ++i) lout[i] = l[i];
}

__global__ __launch_bounds__(256) void attn_kernel(
    const float* __restrict__ Q, const float* __restrict__ K, const float* __restrict__ V,
    const float* __restrict__ KY, const float* __restrict__ VY,
    const float* __restrict__ gate, float* __restrict__ O)
{
    extern __shared__ float smf[];
    float* Qs  = smf + SM_QS;
    float* KsT = smf + SM_KT;
    float* Vs  = smf + SM_VS;
    float* Ps  = smf + SM_PS;

    const int qt = blockIdx.x, h = blockIdx.y, b = blockIdx.z;
    const int t = threadIdx.x;
    const int tx = t & 15, ty = t >> 4, lane = t & 31, wrp = t >> 5;
    const int hoff = h * 128;
    const size_t qrow0 = (size_t)b * 2048 + (size_t)qt * 64;

    const float* Qb = Q + qrow0 * 2048 + hoff;
#pragma unroll
    for (int p = 0; p < 8; ++p) {
        int tok = wrp + p * 8;
        *(float4*)(Qs + tok * 132 + lane * 4) =
            *(const float4*)(Qb + (size_t)tok * 2048 + lane * 4);
    }
    // attn_pass begins with __syncthreads() -> Qs is visible before first use

    float acc1[32], acc2[32], l1[4], l2[4];
    attn_pass(K,  V,  (size_t)b * 2048, 32, hoff, Qs, KsT, Vs, Ps, tx, ty, lane, wrp, acc1, l1);
    attn_pass(KY, VY, (size_t)b * 512,   8, hoff, Qs, KsT, Vs, Ps, tx, ty, lane, wrp, acc2, l2);

    const float tg = tanhf(gate[h]);
    float* Ob = O + qrow0 * 2048 + hoff;
#pragma unroll
    for (int i = 0; i < 4; ++i) {
        int qi = 4 * ty + i;
        float inv1 = 1.f / l1[i];
        float inv2 = tg / l2[i];
        float o[8];
#pragma unroll
        for (int dd = 0; dd < 8; ++dd)
            o[dd] = acc1[i * 8 + dd] * inv1 + acc2[i * 8 + dd] * inv2;
        *(float4*)(Ob + (size_t)qi * 2048 + tx * 8)     = *(float4*)(o);
        *(float4*)(Ob + (size_t)qi * 2048 + tx * 8 + 4) = *(float4*)(o + 4);
    }
}

// -------------------------------- host side --------------------------------------
static void launch_sgemm(const float* A, const float* Bm, float* C, int M, int N, int K)
{
    dim3 grid(N / 128, M / 128);
    sgemm_kernel<<<grid, 256>>>(A, Bm, C, M, N, K);
}

extern "C" void kernel_launch(void* const* d_in, const int* in_sizes, int n_in,
                              void* d_out, int out_size)
{
    const float* x    = (const float*)d_in[0];
    // d_in[1]: x_mask (all true; unused)
    const float* fc   = (const float*)d_in[2];
    const float* y    = (const float*)d_in[3];
    // d_in[4]: y_mask (all true; unused)
    const float* wq   = (const float*)d_in[5];
    const float* wk   = (const float*)d_in[6];
    const float* wv   = (const float*)d_in[7];
    const float* wo   = (const float*)d_in[8];
    const float* wky  = (const float*)d_in[9];
    const float* wvy  = (const float*)d_in[10];
    const float* gate = (const float*)d_in[11];
    const float* qnw  = (const float*)d_in[12];
    const float* qnb  = (const float*)d_in[13];
    const float* knw  = (const float*)d_in[14];
    const float* knb  = (const float*)d_in[15];
    const float* kynw = (const float*)d_in[16];
    const float* kynb = (const float*)d_in[17];
    float* out = (float*)d_out;

    float *xq, *xk, *xv, *yk, *yv, *at;
    cudaGetSymbolAddress((void**)&xq, g_xq);
    cudaGetSymbolAddress((void**)&xk, g_xk);
    cudaGetSymbolAddress((void**)&xv, g_xv);
    cudaGetSymbolAddress((void**)&yk, g_yk);
    cudaGetSymbolAddress((void**)&yv, g_yv);
    cudaGetSymbolAddress((void**)&at, g_at);

    // projections
    launch_sgemm(x, wq,  xq, NROWS_X, NH, 2048);
    launch_sgemm(x, wk,  xk, NROWS_X, NH, 2048);
    launch_sgemm(x, wv,  xv, NROWS_X, NH, 2048);
    launch_sgemm(y, wky, yk, NROWS_Y, NH, 2048);
    launch_sgemm(y, wvy, yv, NROWS_Y, NH, 2048);

    // layernorm (+rope)
    ln_rope_kernel<<<NROWS_X, 256>>>(xq, qnw, qnb, fc, 1e-5f, 1);
    ln_rope_kernel<<<NROWS_X, 256>>>(xk, knw, knb, fc, 1e-5f, 1);
    ln_rope_kernel<<<NROWS_Y, 256>>>(yk, kynw, kynb, fc, 1e-6f, 0);

    // fused self + gated-cross attention
    cudaFuncSetAttribute(attn_kernel, cudaFuncAttributeMaxDynamicSharedMemorySize,
                         ATTN_SMEM_FLOATS * 4);
    attn_kernel<<<dim3(32, 16, 2), 256, ATTN_SMEM_FLOATS * 4>>>(xq, xk, xv, yk, yv, gate, at);

    // output projection
    launch_sgemm(at, wo, out, NROWS_X, NH, 2048);
}

// round 2
// speedup vs baseline: 1.7468x; 1.7468x over previous
#include <cuda_runtime.h>
#include <cstdint>
#include <math.h>

// B=2, S=2048, D=2048, H=16, HD=128, LY=512, DY=2048, H*HD=2048
#define NROWS_X 4096
#define NROWS_Y 1024
#define NH      2048

// ---------------- scratch ----------------
__device__ float g_xq[(size_t)NROWS_X * NH];
__device__ float g_xk[(size_t)NROWS_X * NH];
__device__ float g_xv[(size_t)NROWS_X * NH];
__device__ float g_yk[(size_t)NROWS_Y * NH];
__device__ float g_yv[(size_t)NROWS_Y * NH];
__device__ float g_at[(size_t)NROWS_X * NH];

// ---------------- tf32 helpers ----------------
__device__ __forceinline__ uint32_t f2tf(float f) {
    uint32_t u;
    asm("cvt.rna.tf32.f32 %0, %1;" : "=r"(u) : "f"(f));
    return u;
}

__device__ __forceinline__ void mma_tf32(float c[4],
    uint32_t a0, uint32_t a1, uint32_t a2, uint32_t a3,
    uint32_t b0, uint32_t b1)
{
    asm volatile(
        "mma.sync.aligned.m16n8k8.row.col.f32.tf32.tf32.f32 "
        "{%0,%1,%2,%3}, {%4,%5,%6,%7}, {%8,%9}, {%0,%1,%2,%3};"
        : "+f"(c[0]), "+f"(c[1]), "+f"(c[2]), "+f"(c[3])
        : "r"(a0), "r"(a1), "r"(a2), "r"(a3), "r"(b0), "r"(b1));
}

__device__ __forceinline__ float neginf() { return __int_as_float(0xff800000); }

// ================= TF32 GEMM: C[M,N] = A[M,K] @ B[K,N] (row-major) =================
// 128x128x16 tile, 256 threads (8 warps, 2m x 4n), warp = 64x32 (4x4 m16n8k8)
#define G_LDA 20
#define G_LDB 136
__global__ __launch_bounds__(256) void gemm_tf32(
    const float* __restrict__ A, const float* __restrict__ B, float* __restrict__ C,
    int M, int N, int K)
{
    __shared__ uint32_t As[128 * G_LDA];
    __shared__ uint32_t Bs[16 * G_LDB];
    const int t = threadIdx.x, lane = t & 31, wid = t >> 5;
    const int wm = wid >> 2, wn = wid & 3;
    const int g = lane >> 2, c = lane & 3;
    const int m0 = blockIdx.y * 128, n0 = blockIdx.x * 128;

    float acc[4][4][4];
#pragma unroll
    for (int i = 0; i < 4; ++i)
#pragma unroll
        for (int j = 0; j < 4; ++j)
#pragma unroll
            for (int k = 0; k < 4; ++k) acc[i][j][k] = 0.f;

    const float* Ap = A + (size_t)(m0 + (t >> 1)) * K + (t & 1) * 8;
    const float* Bp = B + (size_t)(t >> 4) * N + n0 + (t & 15) * 8;
    const int as0 = (t >> 1) * G_LDA + (t & 1) * 8;
    const int bs0 = (t >> 4) * G_LDB + (t & 15) * 8;

    for (int k0 = 0; k0 < K; k0 += 16) {
        float4 af0 = *(const float4*)(Ap);
        float4 af1 = *(const float4*)(Ap + 4);
        float4 bf0 = *(const float4*)(Bp);
        float4 bf1 = *(const float4*)(Bp + 4);
        Ap += 16;
        Bp += (size_t)16 * N;
        __syncthreads();
        {
            uint4 u0 = make_uint4(f2tf(af0.x), f2tf(af0.y), f2tf(af0.z), f2tf(af0.w));
            uint4 u1 = make_uint4(f2tf(af1.x), f2tf(af1.y), f2tf(af1.z), f2tf(af1.w));
            *(uint4*)(As + as0)     = u0;
            *(uint4*)(As + as0 + 4) = u1;
            uint4 v0 = make_uint4(f2tf(bf0.x), f2tf(bf0.y), f2tf(bf0.z), f2tf(bf0.w));
            uint4 v1 = make_uint4(f2tf(bf1.x), f2tf(bf1.y), f2tf(bf1.z), f2tf(bf1.w));
            *(uint4*)(Bs + bs0)     = v0;
            *(uint4*)(Bs + bs0 + 4) = v1;
        }
        __syncthreads();
#pragma unroll
        for (int ks = 0; ks < 2; ++ks) {
            uint32_t a[4][4];
#pragma unroll
            for (int mi = 0; mi < 4; ++mi) {
                int ab = (wm * 64 + mi * 16 + g) * G_LDA + ks * 8 + c;
                a[mi][0] = As[ab];
                a[mi][1] = As[ab + 8 * G_LDA];
                a[mi][2] = As[ab + 4];
                a[mi][3] = As[ab + 8 * G_LDA + 4];
            }
#pragma unroll
            for (int ni = 0; ni < 4; ++ni) {
                int bb = (ks * 8 + c) * G_LDB + wn * 32 + ni * 8 + g;
                uint32_t b0 = Bs[bb], b1 = Bs[bb + 4 * G_LDB];
#pragma unroll
                for (int mi = 0; mi < 4; ++mi)
                    mma_tf32(acc[mi][ni], a[mi][0], a[mi][1], a[mi][2], a[mi][3], b0, b1);
            }
        }
    }
#pragma unroll
    for (int mi = 0; mi < 4; ++mi)
#pragma unroll
        for (int ni = 0; ni < 4; ++ni) {
            int row = m0 + wm * 64 + mi * 16 + g;
            int col = n0 + wn * 32 + ni * 8 + 2 * c;
            *(float2*)&C[(size_t)row * N + col] =
                make_float2(acc[mi][ni][0], acc[mi][ni][1]);
            *(float2*)&C[(size_t)(row + 8) * N + col] =
                make_float2(acc[mi][ni][2], acc[mi][ni][3]);
        }
}

// --------------- LayerNorm (+ optional RoPE), in place, one block per row --------
__global__ __launch_bounds__(256) void ln_rope_kernel(
    float* __restrict__ X, const float* __restrict__ w, const float* __restrict__ bgain,
    const float* __restrict__ fc, float eps, int do_rope)
{
    const int row = blockIdx.x;
    float* xr = X + (size_t)row * 2048;
    const int t = threadIdx.x;

    float v[8];
    *(float4*)(v)     = *(const float4*)(xr + t * 8);
    *(float4*)(v + 4) = *(const float4*)(xr + t * 8 + 4);

    float s = 0.f, ss = 0.f;
#pragma unroll
    for (int i = 0; i < 8; ++i) { s += v[i]; ss += v[i] * v[i]; }
#pragma unroll
    for (int off = 16; off; off >>= 1) {
        s  += __shfl_xor_sync(0xffffffffu, s, off);
        ss += __shfl_xor_sync(0xffffffffu, ss, off);
    }
    __shared__ float sh[16];
    const int lane = t & 31, wrp = t >> 5;
    if (lane == 0) { sh[wrp] = s; sh[8 + wrp] = ss; }
    __syncthreads();
    s = 0.f; ss = 0.f;
#pragma unroll
    for (int i = 0; i < 8; ++i) { s += sh[i]; ss += sh[8 + i]; }

    const float mean = s * (1.f / 2048.f);
    const float var  = ss * (1.f / 2048.f) - mean * mean;
    const float rs   = rsqrtf(var + eps);

    const int base = t * 8;
    float o[8];
#pragma unroll
    for (int i = 0; i < 8; ++i) {
        int e = base + i;
        o[i] = (v[i] - mean) * rs * w[e] + bgain[e];
    }
    if (do_rope) {
        int sidx = row & 2047;
#pragma unroll
        for (int i = 0; i < 8; i += 2) {
            int e = base + i;
            int pidx = (e & 127) >> 1;
            float cc = fc[(sidx * 64 + pidx) * 2 + 0];
            float sn = fc[(sidx * 64 + pidx) * 2 + 1];
            float r0 = o[i] * cc - o[i + 1] * sn;
            float r1 = o[i] * sn + o[i + 1] * cc;
            o[i] = r0; o[i + 1] = r1;
        }
    }
    *(float4*)(xr + t * 8)     = *(float4*)(o);
    *(float4*)(xr + t * 8 + 4) = *(float4*)(o + 4);
}

// ================= TF32 flash attention (self + gated cross) =================
// Block: (qtile64, h, b), 128 threads (4 warps, 16 q-rows each). KV tile = 32.
#define A_LDQ 140
#define A_LDK 132
#define A_LDV 35
#define A_LDP 44
#define A_QS  0
#define A_KS  (64 * A_LDQ)
#define A_VS  (A_KS + 32 * A_LDK)
#define A_PS  (A_VS + 128 * A_LDV)
#define A_TOT (A_PS + 64 * A_LDP)   // 20480 words = 81920 bytes

__device__ __forceinline__ void attn_pass_tc(
    const float* __restrict__ Kg, const float* __restrict__ Vg,
    size_t kv0, int ntiles, int hoff,
    uint32_t* Qs, uint32_t* Ks, uint32_t* Vs, uint32_t* Ps,
    int t, float acc[16][4], float lout[2])
{
    const int lane = t & 31, wid = t >> 5;
    const int g = lane >> 2, c = lane & 3;
    float m0 = neginf(), m1 = neginf();
    float l0 = 0.f, l1 = 0.f;
#pragma unroll
    for (int i = 0; i < 16; ++i)
#pragma unroll
        for (int j = 0; j < 4; ++j) acc[i][j] = 0.f;

    for (int kt = 0; kt < ntiles; ++kt) {
        __syncthreads();   // prev-tile consumers of Ks/Vs done (and Qs visible on iter 0)
        const float* Kb = Kg + (kv0 + (size_t)kt * 32) * 2048 + hoff;
        const float* Vb = Vg + (kv0 + (size_t)kt * 32) * 2048 + hoff;
#pragma unroll
        for (int p = 0; p < 8; ++p) {
            int f = p * 128 + t;
            int row = f >> 5, c4 = f & 31;
            float4 k4 = *(const float4*)(Kb + (size_t)row * 2048 + c4 * 4);
            uint4 u = make_uint4(f2tf(k4.x), f2tf(k4.y), f2tf(k4.z), f2tf(k4.w));
            *(uint4*)(Ks + row * A_LDK + c4 * 4) = u;
        }
#pragma unroll
        for (int p = 0; p < 8; ++p) {
            int tok = wid * 8 + p;
            float4 v4 = *(const float4*)(Vb + (size_t)tok * 2048 + lane * 4);
            Vs[(lane * 4 + 0) * A_LDV + tok] = f2tf(v4.x);
            Vs[(lane * 4 + 1) * A_LDV + tok] = f2tf(v4.y);
            Vs[(lane * 4 + 2) * A_LDV + tok] = f2tf(v4.z);
            Vs[(lane * 4 + 3) * A_LDV + tok] = f2tf(v4.w);
        }
        __syncthreads();

        // ---- S = Q @ K^T  (16q x 32k per warp) ----
        float s[4][4];
#pragma unroll
        for (int ni = 0; ni < 4; ++ni)
#pragma unroll
            for (int j = 0; j < 4; ++j) s[ni][j] = 0.f;
#pragma unroll
        for (int ks = 0; ks < 16; ++ks) {
            int ab = (wid * 16 + g) * A_LDQ + ks * 8 + c;
            uint32_t a0 = Qs[ab], a1 = Qs[ab + 8 * A_LDQ];
            uint32_t a2 = Qs[ab + 4], a3 = Qs[ab + 8 * A_LDQ + 4];
#pragma unroll
            for (int ni = 0; ni < 4; ++ni) {
                int bb = (ni * 8 + g) * A_LDK + ks * 8 + c;
                mma_tf32(s[ni], a0, a1, a2, a3, Ks[bb], Ks[bb + 4]);
            }
        }

        // ---- online softmax (rows g and g+8 of this warp's 16) ----
        float rm0 = neginf(), rm1 = neginf();
#pragma unroll
        for (int ni = 0; ni < 4; ++ni) {
            rm0 = fmaxf(rm0, fmaxf(s[ni][0], s[ni][1]));
            rm1 = fmaxf(rm1, fmaxf(s[ni][2], s[ni][3]));
        }
#pragma unroll
        for (int off = 1; off <= 2; off <<= 1) {
            rm0 = fmaxf(rm0, __shfl_xor_sync(0xffffffffu, rm0, off));
            rm1 = fmaxf(rm1, __shfl_xor_sync(0xffffffffu, rm1, off));
        }
        float mn0 = fmaxf(m0, rm0), mn1 = fmaxf(m1, rm1);
        float co0 = __expf(m0 - mn0), co1 = __expf(m1 - mn1);
        float rs0 = 0.f, rs1 = 0.f;
        __syncwarp();   // prior PV reads of Ps done before overwrite
#pragma unroll
        for (int ni = 0; ni < 4; ++ni) {
            float p00 = __expf(s[ni][0] - mn0);
            float p01 = __expf(s[ni][1] - mn0);
            float p10 = __expf(s[ni][2] - mn1);
            float p11 = __expf(s[ni][3] - mn1);
            rs0 += p00 + p01;
            rs1 += p10 + p11;
            int pb = (wid * 16 + g) * A_LDP + ni * 8 + 2 * c;
            Ps[pb]     = f2tf(p00);
            Ps[pb + 1] = f2tf(p01);
            Ps[pb + 8 * A_LDP]     = f2tf(p10);
            Ps[pb + 8 * A_LDP + 1] = f2tf(p11);
        }
        __syncwarp();
#pragma unroll
        for (int off = 1; off <= 2; off <<= 1) {
            rs0 += __shfl_xor_sync(0xffffffffu, rs0, off);
            rs1 += __shfl_xor_sync(0xffffffffu, rs1, off);
        }
        l0 = l0 * co0 + rs0;
        l1 = l1 * co1 + rs1;
        m0 = mn0; m1 = mn1;
#pragma unroll
        for (int ni = 0; ni < 16; ++ni) {
            acc[ni][0] *= co0; acc[ni][1] *= co0;
            acc[ni][2] *= co1; acc[ni][3] *= co1;
        }

        // ---- O += P @ V  (16q x 128d per warp, k=32) ----
#pragma unroll
        for (int ks = 0; ks < 4; ++ks) {
            int ab = (wid * 16 + g) * A_LDP + ks * 8 + c;
            uint32_t a0 = Ps[ab], a1 = Ps[ab + 8 * A_LDP];
            uint32_t a2 = Ps[ab + 4], a3 = Ps[ab + 8 * A_LDP + 4];
#pragma unroll
            for (int ni = 0; ni < 16; ++ni) {
                int bb = (ni * 8 + g) * A_LDV + ks * 8 + c;
                mma_tf32(acc[ni], a0, a1, a2, a3, Vs[bb], Vs[bb + 4]);
            }
        }
    }
    lout[0] = l0; lout[1] = l1;
}

__global__ __launch_bounds__(128) void attn_tc_kernel(
    const float* __restrict__ Q, const float* __restrict__ K, const float* __restrict__ V,
    const float* __restrict__ KY, const float* __restrict__ VY,
    const float* __restrict__ gate, float* __restrict__ O)
{
    extern __shared__ uint32_t sm[];
    uint32_t* Qs = sm + A_QS;
    uint32_t* Ks = sm + A_KS;
    uint32_t* Vs = sm + A_VS;
    uint32_t* Ps = sm + A_PS;

    const int qt = blockIdx.x, h = blockIdx.y, b = blockIdx.z;
    const int t = threadIdx.x, lane = t & 31, wid = t >> 5;
    const int g = lane >> 2, c = lane & 3;
    const int hoff = h * 128;
    const size_t qrow0 = (size_t)b * 2048 + (size_t)qt * 64;
    const float scale = 0.08838834764831845f;  // 1/sqrt(128)

    const float* Qb = Q + qrow0 * 2048 + hoff;
#pragma unroll
    for (int p = 0; p < 16; ++p) {
        int f = p * 128 + t;
        int row = f >> 5, c4 = f & 31;
        float4 q4 = *(const float4*)(Qb + (size_t)row * 2048 + c4 * 4);
        uint4 u = make_uint4(f2tf(q4.x * scale), f2tf(q4.y * scale),
                             f2tf(q4.z * scale), f2tf(q4.w * scale));
        *(uint4*)(Qs + row * A_LDQ + c4 * 4) = u;
    }
    // first __syncthreads inside attn_pass_tc publishes Qs

    float acc[16][4], l[2];

    // ---- self attention ----
    attn_pass_tc(K, V, (size_t)b * 2048, 64, hoff, Qs, Ks, Vs, Ps, t, acc, l);
    float* Ob = O + qrow0 * 2048 + hoff;
    {
        float inv0 = 1.f / l[0], inv1 = 1.f / l[1];
        int row = wid * 16 + g;
#pragma unroll
        for (int ni = 0; ni < 16; ++ni) {
            int col = ni * 8 + 2 * c;
            *(float2*)(Ob + (size_t)row * 2048 + col) =
                make_float2(acc[ni][0] * inv0, acc[ni][1] * inv0);
            *(float2*)(Ob + (size_t)(row + 8) * 2048 + col) =
                make_float2(acc[ni][2] * inv1, acc[ni][3] * inv1);
        }
    }

    // ---- gated cross attention (same thread re-reads its own writes) ----
    attn_pass_tc(KY, VY, (size_t)b * 512, 16, hoff, Qs, Ks, Vs, Ps, t, acc, l);
    {
        float tg = tanhf(gate[h]);
        float inv0 = tg / l[0], inv1 = tg / l[1];
        int row = wid * 16 + g;
#pragma unroll
        for (int ni = 0; ni < 16; ++ni) {
            int col = ni * 8 + 2 * c;
            float2 p0 = *(float2*)(Ob + (size_t)row * 2048 + col);
            float2 p1 = *(float2*)(Ob + (size_t)(row + 8) * 2048 + col);
            *(float2*)(Ob + (size_t)row * 2048 + col) =
                make_float2(p0.x + acc[ni][0] * inv0, p0.y + acc[ni][1] * inv0);
            *(float2*)(Ob + (size_t)(row + 8) * 2048 + col) =
                make_float2(p1.x + acc[ni][2] * inv1, p1.y + acc[ni][3] * inv1);
        }
    }
}

// -------------------------------- host side --------------------------------------
static void launch_gemm(const float* A, const float* B, float* C, int M, int N, int K)
{
    dim3 grid(N / 128, M / 128);
    gemm_tf32<<<grid, 256>>>(A, B, C, M, N, K);
}

extern "C" void kernel_launch(void* const* d_in, const int* in_sizes, int n_in,
                              void* d_out, int out_size)
{
    const float* x    = (const float*)d_in[0];
    const float* fc   = (const float*)d_in[2];
    const float* y    = (const float*)d_in[3];
    const float* wq   = (const float*)d_in[5];
    const float* wk   = (const float*)d_in[6];
    const float* wv   = (const float*)d_in[7];
    const float* wo   = (const float*)d_in[8];
    const float* wky  = (const float*)d_in[9];
    const float* wvy  = (const float*)d_in[10];
    const float* gate = (const float*)d_in[11];
    const float* qnw  = (const float*)d_in[12];
    const float* qnb  = (const float*)d_in[13];
    const float* knw  = (const float*)d_in[14];
    const float* knb  = (const float*)d_in[15];
    const float* kynw = (const float*)d_in[16];
    const float* kynb = (const float*)d_in[17];
    float* out = (float*)d_out;

    float *xq, *xk, *xv, *yk, *yv, *at;
    cudaGetSymbolAddress((void**)&xq, g_xq);
    cudaGetSymbolAddress((void**)&xk, g_xk);
    cudaGetSymbolAddress((void**)&xv, g_xv);
    cudaGetSymbolAddress((void**)&yk, g_yk);
    cudaGetSymbolAddress((void**)&yv, g_yv);
    cudaGetSymbolAddress((void**)&at, g_at);

    // projections (tf32 tensor cores)
    launch_gemm(x, wq,  xq, NROWS_X, NH, 2048);
    launch_gemm(x, wk,  xk, NROWS_X, NH, 2048);
    launch_gemm(x, wv,  xv, NROWS_X, NH, 2048);
    launch_gemm(y, wky, yk, NROWS_Y, NH, 2048);
    launch_gemm(y, wvy, yv, NROWS_Y, NH, 2048);

    // layernorm (+rope)
    ln_rope_kernel<<<NROWS_X, 256>>>(xq, qnw, qnb, fc, 1e-5f, 1);
    ln_rope_kernel<<<NROWS_X, 256>>>(xk, knw, knb, fc, 1e-5f, 1);
    ln_rope_kernel<<<NROWS_Y, 256>>>(yk, kynw, kynb, fc, 1e-6f, 0);

    // fused self + gated-cross attention (tf32 tensor cores)
    cudaFuncSetAttribute(attn_tc_kernel, cudaFuncAttributeMaxDynamicSharedMemorySize,
                         A_TOT * 4);
    attn_tc_kernel<<<dim3(32, 16, 2), 128, A_TOT * 4>>>(xq, xk, xv, yk, yv, gate, at);

    // output projection
    launch_gemm(at, wo, out, NROWS_X, NH, 2048);
}

// round 4
// speedup vs baseline: 2.8941x; 1.6569x over previous
#include <cuda_runtime.h>
#include <cstdint>
#include <math.h>

// B=2, S=2048, D=2048, H=16, HD=128, LY=512, DY=2048, H*HD=2048
#define NROWS_X 4096
#define NROWS_Y 1024
#define NH      2048

// ---------------- scratch ----------------
__device__ float g_xq[(size_t)NROWS_X * NH];
__device__ float g_xk[(size_t)NROWS_X * NH];
__device__ float g_xv[(size_t)NROWS_X * NH];
__device__ float g_yk[(size_t)NROWS_Y * NH];
__device__ float g_yv[(size_t)NROWS_Y * NH];
__device__ float g_at[(size_t)NROWS_X * NH];

// ---------------- helpers ----------------
__device__ __forceinline__ uint32_t f2tf(float f) {
    uint32_t u;
    asm("cvt.rna.tf32.f32 %0, %1;" : "=r"(u) : "f"(f));
    return u;
}
__device__ __forceinline__ uint32_t bits(float f) { return __float_as_uint(f); }

__device__ __forceinline__ void mma_tf32(float c[4],
    uint32_t a0, uint32_t a1, uint32_t a2, uint32_t a3,
    uint32_t b0, uint32_t b1)
{
    asm volatile(
        "mma.sync.aligned.m16n8k8.row.col.f32.tf32.tf32.f32 "
        "{%0,%1,%2,%3}, {%4,%5,%6,%7}, {%8,%9}, {%0,%1,%2,%3};"
        : "+f"(c[0]), "+f"(c[1]), "+f"(c[2]), "+f"(c[3])
        : "r"(a0), "r"(a1), "r"(a2), "r"(a3), "r"(b0), "r"(b1));
}

__device__ __forceinline__ void cpa16(uint32_t dst, const void* src) {
    asm volatile("cp.async.cg.shared.global [%0], [%1], 16;" :: "r"(dst), "l"(src));
}
__device__ __forceinline__ void cpcommit() { asm volatile("cp.async.commit_group;" ::); }
__device__ __forceinline__ void cpwait2()  { asm volatile("cp.async.wait_group 2;" ::); }

__device__ __forceinline__ float neginf() { return __int_as_float(0xff800000); }

// ================= TF32 GEMM, 4-stage cp.async pipeline =================
// C[M,N] = A[M,K] @ B[K,N], row-major. 128x128x16 tile, 256 thr (8 warps 2x4),
// warp = 64x32 via 4x4 m16n8k8. Raw floats staged; cvt.rna at fragment load.
#define G_LDA 20
#define G_LDB 136
#define GOF_B (4 * 128 * G_LDA)                 // 10240 floats
#define G_TOT (GOF_B + 4 * 16 * G_LDB)          // 18944 floats = 75776 B

__global__ __launch_bounds__(256) void gemm_tf32(
    const float* __restrict__ A, const float* __restrict__ B, float* __restrict__ C,
    int M, int N, int K)
{
    extern __shared__ float gsm[];
    float* As = gsm;
    float* Bs = gsm + GOF_B;

    const int t = threadIdx.x, lane = t & 31, wid = t >> 5;
    const int wm = wid >> 2, wn = wid & 3;
    const int g = lane >> 2, c = lane & 3;
    const int m0 = blockIdx.y * 128, n0 = blockIdx.x * 128;

    const int ar = t >> 1, acol = (t & 1) * 8;
    const int br = t >> 4, bcol = (t & 15) * 8;
    const float* Agp = A + (size_t)(m0 + ar) * K + acol;
    const float* Bgp = B + (size_t)br * N + n0 + bcol;
    const uint32_t aS = (uint32_t)__cvta_generic_to_shared(As + ar * G_LDA + acol);
    const uint32_t bS = (uint32_t)__cvta_generic_to_shared(Bs + br * G_LDB + bcol);
    const int niter = K >> 4;

    float acc[4][4][4];
#pragma unroll
    for (int i = 0; i < 4; ++i)
#pragma unroll
        for (int j = 0; j < 4; ++j)
#pragma unroll
            for (int k = 0; k < 4; ++k) acc[i][j][k] = 0.f;

#define G_FILL(K0) do { \
        int st_ = (K0) & 3; \
        const float* ag_ = Agp + (K0) * 16; \
        const float* bg_ = Bgp + (size_t)(K0) * 16 * N; \
        uint32_t ad_ = aS + st_ * (128 * G_LDA * 4); \
        uint32_t bd_ = bS + st_ * (16 * G_LDB * 4); \
        cpa16(ad_, ag_); cpa16(ad_ + 16, ag_ + 4); \
        cpa16(bd_, bg_); cpa16(bd_ + 16, bg_ + 4); \
    } while (0)

    G_FILL(0); cpcommit();
    G_FILL(1); cpcommit();
    G_FILL(2); cpcommit();

    for (int k0 = 0; k0 < niter; ++k0) {
        cpwait2();
        __syncthreads();
        if (k0 + 3 < niter) G_FILL(k0 + 3);
        cpcommit();

        const float* Ab = As + (k0 & 3) * (128 * G_LDA);
        const float* Bb = Bs + (k0 & 3) * (16 * G_LDB);
#pragma unroll
        for (int ks = 0; ks < 2; ++ks) {
            uint32_t a[4][4];
#pragma unroll
            for (int mi = 0; mi < 4; ++mi) {
                int ab = (wm * 64 + mi * 16 + g) * G_LDA + ks * 8 + c;
                a[mi][0] = f2tf(Ab[ab]);
                a[mi][1] = f2tf(Ab[ab + 8 * G_LDA]);
                a[mi][2] = f2tf(Ab[ab + 4]);
                a[mi][3] = f2tf(Ab[ab + 8 * G_LDA + 4]);
            }
#pragma unroll
            for (int ni = 0; ni < 4; ++ni) {
                int bb = (ks * 8 + c) * G_LDB + wn * 32 + ni * 8 + g;
                uint32_t b0 = f2tf(Bb[bb]), b1 = f2tf(Bb[bb + 4 * G_LDB]);
#pragma unroll
                for (int mi = 0; mi < 4; ++mi)
                    mma_tf32(acc[mi][ni], a[mi][0], a[mi][1], a[mi][2], a[mi][3], b0, b1);
            }
        }
    }
#pragma unroll
    for (int mi = 0; mi < 4; ++mi)
#pragma unroll
        for (int ni = 0; ni < 4; ++ni) {
            int row = m0 + wm * 64 + mi * 16 + g;
            int col = n0 + wn * 32 + ni * 8 + 2 * c;
            *(float2*)&C[(size_t)row * N + col] =
                make_float2(acc[mi][ni][0], acc[mi][ni][1]);
            *(float2*)&C[(size_t)(row + 8) * N + col] =
                make_float2(acc[mi][ni][2], acc[mi][ni][3]);
        }
}

// --------------- LayerNorm (+ optional RoPE), in place, one block per row --------
__global__ __launch_bounds__(256) void ln_rope_kernel(
    float* __restrict__ X, const float* __restrict__ w, const float* __restrict__ bgain,
    const float* __restrict__ fc, float eps, int do_rope)
{
    const int row = blockIdx.x;
    float* xr = X + (size_t)row * 2048;
    const int t = threadIdx.x;

    float v[8];
    *(float4*)(v)     = *(const float4*)(xr + t * 8);
    *(float4*)(v + 4) = *(const float4*)(xr + t * 8 + 4);

    float s = 0.f, ss = 0.f;
#pragma unroll
    for (int i = 0; i < 8; ++i) { s += v[i]; ss += v[i] * v[i]; }
#pragma unroll
    for (int off = 16; off; off >>= 1) {
        s  += __shfl_xor_sync(0xffffffffu, s, off);
        ss += __shfl_xor_sync(0xffffffffu, ss, off);
    }
    __shared__ float sh[16];
    const int lane = t & 31, wrp = t >> 5;
    if (lane == 0) { sh[wrp] = s; sh[8 + wrp] = ss; }
    __syncthreads();
    s = 0.f; ss = 0.f;
#pragma unroll
    for (int i = 0; i < 8; ++i) { s += sh[i]; ss += sh[8 + i]; }

    const float mean = s * (1.f / 2048.f);
    const float var  = ss * (1.f / 2048.f) - mean * mean;
    const float rs   = rsqrtf(var + eps);

    const int base = t * 8;
    float o[8];
#pragma unroll
    for (int i = 0; i < 8; ++i) {
        int e = base + i;
        o[i] = (v[i] - mean) * rs * w[e] + bgain[e];
    }
    if (do_rope) {
        int sidx = row & 2047;
#pragma unroll
        for (int i = 0; i < 8; i += 2) {
            int e = base + i;
            int pidx = (e & 127) >> 1;
            float cc = fc[(sidx * 64 + pidx) * 2 + 0];
            float sn = fc[(sidx * 64 + pidx) * 2 + 1];
            float r0 = o[i] * cc - o[i + 1] * sn;
            float r1 = o[i] * sn + o[i + 1] * cc;
            o[i] = r0; o[i + 1] = r1;
        }
    }
    *(float4*)(xr + t * 8)     = *(float4*)(o);
    *(float4*)(xr + t * 8 + 4) = *(float4*)(o + 4);
}

// ================= TF32 flash attention v2 =================
// 256 threads (8 warps x 16q), TQ=128, KV tile 32, register-staged K/V
// double-buffering (LDG next tile during compute), Q cached in smem for all tiles.
#define AT_LDQ 132
#define AT_LDK 132
#define AT_LDV 136
#define AT_LDP 36
#define AOF_K (128 * AT_LDQ)           // 16896
#define AOF_V (AOF_K + 32 * AT_LDK)    // 21120
#define AOF_P (AOF_V + 32 * AT_LDV)    // 25472
#define AT_TOT (AOF_P + 128 * AT_LDP)  // 30080 floats = 120320 B

__device__ __forceinline__ void attn_pass_tc(
    const float* __restrict__ Kg, const float* __restrict__ Vg,
    size_t kv0, int ntiles, int hoff,
    const float* Qs, float* Ks, float* Vs, float* Ps,
    int t, float acc[16][4], float lout[2])
{
    const int lane = t & 31, wid = t >> 5;
    const int g = lane >> 2, c = lane & 3;
    float m0 = neginf(), m1 = neginf();
    float l0 = 0.f, l1 = 0.f;
#pragma unroll
    for (int i = 0; i < 16; ++i)
#pragma unroll
        for (int j = 0; j < 4; ++j) acc[i][j] = 0.f;

    float rK[16], rV[16];
    // prologue: stage tile 0 in registers
    {
        const float* Kb = Kg + kv0 * 2048 + hoff;
        const float* Vb = Vg + kv0 * 2048 + hoff;
#pragma unroll
        for (int j = 0; j < 4; ++j) {
            *(float4*)&rK[j * 4] = *(const float4*)(Kb + (size_t)(8 * j + wid) * 2048 + lane * 4);
            *(float4*)&rV[j * 4] = *(const float4*)(Vb + (size_t)(8 * j + wid) * 2048 + lane * 4);
        }
    }

    for (int kt = 0; kt < ntiles; ++kt) {
        __syncthreads();   // all warps done with previous tile's smem
        // commit staged tile (cvt.rna once per element)
#pragma unroll
        for (int j = 0; j < 4; ++j) {
            uint4 uk = make_uint4(f2tf(rK[j * 4]), f2tf(rK[j * 4 + 1]),
                                  f2tf(rK[j * 4 + 2]), f2tf(rK[j * 4 + 3]));
            *(uint4*)(Ks + (8 * j + wid) * AT_LDK + lane * 4) = uk;
            uint4 uv = make_uint4(f2tf(rV[j * 4]), f2tf(rV[j * 4 + 1]),
                                  f2tf(rV[j * 4 + 2]), f2tf(rV[j * 4 + 3]));
            *(uint4*)(Vs + (8 * j + wid) * AT_LDV + lane * 4) = uv;
        }
        __syncthreads();   // tile visible
        // prefetch next tile into registers (overlaps compute below)
        if (kt + 1 < ntiles) {
            const float* Kb = Kg + (kv0 + (size_t)(kt + 1) * 32) * 2048 + hoff;
            const float* Vb = Vg + (kv0 + (size_t)(kt + 1) * 32) * 2048 + hoff;
#pragma unroll
            for (int j = 0; j < 4; ++j) {
                *(float4*)&rK[j * 4] = *(const float4*)(Kb + (size_t)(8 * j + wid) * 2048 + lane * 4);
                *(float4*)&rV[j * 4] = *(const float4*)(Vb + (size_t)(8 * j + wid) * 2048 + lane * 4);
            }
        }

        // ---- S = Q @ K^T  (16q x 32k per warp) ----
        float s[4][4];
#pragma unroll
        for (int ni = 0; ni < 4; ++ni)
#pragma unroll
            for (int j = 0; j < 4; ++j) s[ni][j] = 0.f;
#pragma unroll
        for (int ks = 0; ks < 16; ++ks) {
            int ab = (wid * 16 + g) * AT_LDQ + ks * 8 + c;
            uint32_t a0 = bits(Qs[ab]), a1 = bits(Qs[ab + 8 * AT_LDQ]);
            uint32_t a2 = bits(Qs[ab + 4]), a3 = bits(Qs[ab + 8 * AT_LDQ + 4]);
#pragma unroll
            for (int ni = 0; ni < 4; ++ni) {
                int bb = (ni * 8 + g) * AT_LDK + ks * 8 + c;
                mma_tf32(s[ni], a0, a1, a2, a3, bits(Ks[bb]), bits(Ks[bb + 4]));
            }
        }

        // ---- online softmax (rows g and g+8 of this warp's 16) ----
        float rm0 = neginf(), rm1 = neginf();
#pragma unroll
        for (int ni = 0; ni < 4; ++ni) {
            rm0 = fmaxf(rm0, fmaxf(s[ni][0], s[ni][1]));
            rm1 = fmaxf(rm1, fmaxf(s[ni][2], s[ni][3]));
        }
#pragma unroll
        for (int off = 1; off <= 2; off <<= 1) {
            rm0 = fmaxf(rm0, __shfl_xor_sync(0xffffffffu, rm0, off));
            rm1 = fmaxf(rm1, __shfl_xor_sync(0xffffffffu, rm1, off));
        }
        float mn0 = fmaxf(m0, rm0), mn1 = fmaxf(m1, rm1);
        float co0 = __expf(m0 - mn0), co1 = __expf(m1 - mn1);
        float rs0 = 0.f, rs1 = 0.f;
        __syncwarp();   // prior PV reads of this warp's P rows done
#pragma unroll
        for (int ni = 0; ni < 4; ++ni) {
            float p00 = __expf(s[ni][0] - mn0);
            float p01 = __expf(s[ni][1] - mn0);
            float p10 = __expf(s[ni][2] - mn1);
            float p11 = __expf(s[ni][3] - mn1);
            rs0 += p00 + p01;
            rs1 += p10 + p11;
            int pb = (wid * 16 + g) * AT_LDP + ni * 8 + 2 * c;
            Ps[pb]     = __uint_as_float(f2tf(p00));
            Ps[pb + 1] = __uint_as_float(f2tf(p01));
            Ps[pb + 8 * AT_LDP]     = __uint_as_float(f2tf(p10));
            Ps[pb + 8 * AT_LDP + 1] = __uint_as_float(f2tf(p11));
        }
        __syncwarp();
#pragma unroll
        for (int off = 1; off <= 2; off <<= 1) {
            rs0 += __shfl_xor_sync(0xffffffffu, rs0, off);
            rs1 += __shfl_xor_sync(0xffffffffu, rs1, off);
        }
        l0 = l0 * co0 + rs0;
        l1 = l1 * co1 + rs1;
        m0 = mn0; m1 = mn1;
#pragma unroll
        for (int ni = 0; ni < 16; ++ni) {
            acc[ni][0] *= co0; acc[ni][1] *= co0;
            acc[ni][2] *= co1; acc[ni][3] *= co1;
        }

        // ---- O += P @ V  (16q x 128d per warp, k=32) ----
#pragma unroll
        for (int ks = 0; ks < 4; ++ks) {
            int ab = (wid * 16 + g) * AT_LDP + ks * 8 + c;
            uint32_t a0 = bits(Ps[ab]), a1 = bits(Ps[ab + 8 * AT_LDP]);
            uint32_t a2 = bits(Ps[ab + 4]), a3 = bits(Ps[ab + 8 * AT_LDP + 4]);
#pragma unroll
            for (int ni = 0; ni < 16; ++ni) {
                int bb = (ks * 8 + c) * AT_LDV + ni * 8 + g;
                mma_tf32(acc[ni], a0, a1, a2, a3, bits(Vs[bb]), bits(Vs[bb + 4 * AT_LDV]));
            }
        }
    }
    lout[0] = l0; lout[1] = l1;
}

__global__ __launch_bounds__(256) void attn_tc_kernel(
    const float* __restrict__ Q, const float* __restrict__ K, const float* __restrict__ V,
    const float* __restrict__ KY, const float* __restrict__ VY,
    const float* __restrict__ gate, float* __restrict__ O)
{
    extern __shared__ float smf[];
    float* Qs = smf;
    float* Ks = smf + AOF_K;
    float* Vs = smf + AOF_V;
    float* Ps = smf + AOF_P;

    const int qt = blockIdx.x, h = blockIdx.y, b = blockIdx.z;
    const int t = threadIdx.x, lane = t & 31, wid = t >> 5;
    const int g = lane >> 2, c = lane & 3;
    const int hoff = h * 128;
    const size_t qrow0 = (size_t)b * 2048 + (size_t)qt * 128;
    const float scale = 0.08838834764831845f;  // 1/sqrt(128)

    // Q fill: scale + cvt once; reused across all 80 KV tiles
    const float* Qb = Q + qrow0 * 2048 + hoff;
#pragma unroll
    for (int i = 0; i < 16; ++i) {
        int id = i * 256 + t;
        int row = id >> 5, c4 = id & 31;
        float4 q4 = *(const float4*)(Qb + (size_t)row * 2048 + c4 * 4);
        uint4 u = make_uint4(f2tf(q4.x * scale), f2tf(q4.y * scale),
                             f2tf(q4.z * scale), f2tf(q4.w * scale));
        *(uint4*)(Qs + row * AT_LDQ + c4 * 4) = u;
    }
    // first __syncthreads inside attn_pass_tc publishes Qs

    float acc[16][4], l[2];

    // ---- self attention ----
    attn_pass_tc(K, V, (size_t)b * 2048, 64, hoff, Qs, Ks, Vs, Ps, t, acc, l);
    float* Ob = O + qrow0 * 2048 + hoff;
    {
        float inv0 = 1.f / l[0], inv1 = 1.f / l[1];
        int row = wid * 16 + g;
#pragma unroll
        for (int ni = 0; ni < 16; ++ni) {
            int col = ni * 8 + 2 * c;
            *(float2*)(Ob + (size_t)row * 2048 + col) =
                make_float2(acc[ni][0] * inv0, acc[ni][1] * inv0);
            *(float2*)(Ob + (size_t)(row + 8) * 2048 + col) =
                make_float2(acc[ni][2] * inv1, acc[ni][3] * inv1);
        }
    }

    // ---- gated cross attention (same thread re-reads its own writes) ----
    attn_pass_tc(KY, VY, (size_t)b * 512, 16, hoff, Qs, Ks, Vs, Ps, t, acc, l);
    {
        float tg = tanhf(gate[h]);
        float inv0 = tg / l[0], inv1 = tg / l[1];
        int row = wid * 16 + g;
#pragma unroll
        for (int ni = 0; ni < 16; ++ni) {
            int col = ni * 8 + 2 * c;
            float2 p0 = *(float2*)(Ob + (size_t)row * 2048 + col);
            float2 p1 = *(float2*)(Ob + (size_t)(row + 8) * 2048 + col);
            *(float2*)(Ob + (size_t)row * 2048 + col) =
                make_float2(p0.x + acc[ni][0] * inv0, p0.y + acc[ni][1] * inv0);
            *(float2*)(Ob + (size_t)(row + 8) * 2048 + col) =
                make_float2(p1.x + acc[ni][2] * inv1, p1.y + acc[ni][3] * inv1);
        }
    }
}

// -------------------------------- host side --------------------------------------
static void launch_gemm(const float* A, const float* B, float* C, int M, int N, int K)
{
    dim3 grid(N / 128, M / 128);
    gemm_tf32<<<grid, 256, G_TOT * 4>>>(A, B, C, M, N, K);
}

extern "C" void kernel_launch(void* const* d_in, const int* in_sizes, int n_in,
                              void* d_out, int out_size)
{
    const float* x    = (const float*)d_in[0];
    const float* fc   = (const float*)d_in[2];
    const float* y    = (const float*)d_in[3];
    const float* wq   = (const float*)d_in[5];
    const float* wk   = (const float*)d_in[6];
    const float* wv   = (const float*)d_in[7];
    const float* wo   = (const float*)d_in[8];
    const float* wky  = (const float*)d_in[9];
    const float* wvy  = (const float*)d_in[10];
    const float* gate = (const float*)d_in[11];
    const float* qnw  = (const float*)d_in[12];
    const float* qnb  = (const float*)d_in[13];
    const float* knw  = (const float*)d_in[14];
    const float* knb  = (const float*)d_in[15];
    const float* kynw = (const float*)d_in[16];
    const float* kynb = (const float*)d_in[17];
    float* out = (float*)d_out;

    float *xq, *xk, *xv, *yk, *yv, *at;
    cudaGetSymbolAddress((void**)&xq, g_xq);
    cudaGetSymbolAddress((void**)&xk, g_xk);
    cudaGetSymbolAddress((void**)&xv, g_xv);
    cudaGetSymbolAddress((void**)&yk, g_yk);
    cudaGetSymbolAddress((void**)&yv, g_yv);
    cudaGetSymbolAddress((void**)&at, g_at);

    cudaFuncSetAttribute(gemm_tf32, cudaFuncAttributeMaxDynamicSharedMemorySize, G_TOT * 4);
    cudaFuncSetAttribute(attn_tc_kernel, cudaFuncAttributeMaxDynamicSharedMemorySize, AT_TOT * 4);

    // projections (tf32 tensor cores, cp.async pipelined)
    launch_gemm(x, wq,  xq, NROWS_X, NH, 2048);
    launch_gemm(x, wk,  xk, NROWS_X, NH, 2048);
    launch_gemm(x, wv,  xv, NROWS_X, NH, 2048);
    launch_gemm(y, wky, yk, NROWS_Y, NH, 2048);
    launch_gemm(y, wvy, yv, NROWS_Y, NH, 2048);

    // layernorm (+rope)
    ln_rope_kernel<<<NROWS_X, 256>>>(xq, qnw, qnb, fc, 1e-5f, 1);
    ln_rope_kernel<<<NROWS_X, 256>>>(xk, knw, knb, fc, 1e-5f, 1);
    ln_rope_kernel<<<NROWS_Y, 256>>>(yk, kynw, kynb, fc, 1e-6f, 0);

    // fused self + gated-cross attention
    attn_tc_kernel<<<dim3(16, 16, 2), 256, AT_TOT * 4>>>(xq, xk, xv, yk, yv, gate, at);

    // output projection
    launch_gemm(at, wo, out, NROWS_X, NH, 2048);
}